// round 15
// baseline (speedup 1.0000x reference)
#include <cuda_runtime.h>
#include <cstdint>

#define NROWS 16384
#define DDIM  32
#define HDIM  128
#define BK    32                 // K floats per sub-tile -> 128B rows
#define BN    32                 // B rows: 32 msg cols (degree from A-side FADD)
#define STAGES 5                 // each stage = 2 sub-tiles (64 k-floats)
#define NT2   (NROWS / (2 * BK)) // 256 double-tiles
#define SUBA  (128 * 128)        // 16384 per A sub-tile
#define SUBB  (BN * 128)         // 4096 per B sub-tile
#define STAGE_BYTES (2 * SUBA + 2 * SUBB)           // 40960
#define SMEM_TOTAL  (1024 + STAGES * STAGE_BYTES)   // 205824

// device scratch
__device__ float g_msgB[BN * NROWS];   // [col][k]; 32 tf32 msg columns

// ---------------- PTX helpers ----------------
__device__ __forceinline__ void cp16(uint32_t dst, const void* src) {
    asm volatile("cp.async.cg.shared.global [%0], [%1], 16;" :: "r"(dst), "l"(src) : "memory");
}
__device__ __forceinline__ float tf32_rna(float x) {
    uint32_t r;
    asm("cvt.rna.tf32.f32 %0, %1;" : "=r"(r) : "f"(x));
    return __uint_as_float(r);
}
__device__ __forceinline__ void ldsm_x4(uint32_t& r0, uint32_t& r1, uint32_t& r2, uint32_t& r3,
                                        uint32_t addr) {
    asm volatile("ldmatrix.sync.aligned.m8n8.x4.shared.b16 {%0,%1,%2,%3}, [%4];"
                 : "=r"(r0), "=r"(r1), "=r"(r2), "=r"(r3) : "r"(addr));
}
__device__ __forceinline__ void mma_tf32(float* c, uint32_t a0, uint32_t a1,
                                         uint32_t a2, uint32_t a3,
                                         uint32_t b0, uint32_t b1) {
    asm volatile(
        "mma.sync.aligned.m16n8k8.row.col.f32.tf32.tf32.f32 "
        "{%0,%1,%2,%3}, {%4,%5,%6,%7}, {%8,%9}, {%0,%1,%2,%3};"
        : "+f"(c[0]), "+f"(c[1]), "+f"(c[2]), "+f"(c[3])
        : "r"(a0), "r"(a1), "r"(a2), "r"(a3), "r"(b0), "r"(b1));
}

// ==================== Kernel 1: message MLP (round-9 proven) ====================
__global__ __launch_bounds__(128) void msg_kernel(
    const float* __restrict__ states, const float* __restrict__ W1,
    const float* __restrict__ b1,     const float* __restrict__ W2,
    const float* __restrict__ b2)
{
    __shared__ float sW1[DDIM * HDIM];
    __shared__ float sW2[HDIM * DDIM];
    const int tid = threadIdx.x;
    for (int i = tid; i < DDIM * HDIM; i += 128) sW1[i] = W1[i];
    for (int i = tid; i < HDIM * DDIM; i += 128) sW2[i] = W2[i];
    __syncthreads();

    const int row = blockIdx.x * 128 + tid;
    float s[DDIM];
    const float4* sp = reinterpret_cast<const float4*>(states + (size_t)row * DDIM);
    #pragma unroll
    for (int j4 = 0; j4 < DDIM / 4; j4++) {
        float4 v = sp[j4];
        s[4*j4+0] = v.x; s[4*j4+1] = v.y; s[4*j4+2] = v.z; s[4*j4+3] = v.w;
    }
    float m[DDIM];
    #pragma unroll
    for (int d = 0; d < DDIM; d++) m[d] = __ldg(&b2[d]);

    #pragma unroll 4
    for (int hg = 0; hg < HDIM / 4; hg++) {
        float4 hid = __ldg(reinterpret_cast<const float4*>(b1) + hg);
        #pragma unroll
        for (int j = 0; j < DDIM; j++) {
            float4 w = *reinterpret_cast<const float4*>(&sW1[j * HDIM + 4 * hg]);
            hid.x += s[j] * w.x; hid.y += s[j] * w.y;
            hid.z += s[j] * w.z; hid.w += s[j] * w.w;
        }
        float rr[4] = {fmaxf(hid.x, 0.f), fmaxf(hid.y, 0.f),
                       fmaxf(hid.z, 0.f), fmaxf(hid.w, 0.f)};
        #pragma unroll
        for (int e = 0; e < 4; e++) {
            float r = rr[e];
            #pragma unroll
            for (int d4 = 0; d4 < DDIM / 4; d4++) {
                float4 w = *reinterpret_cast<const float4*>(&sW2[(4*hg+e) * DDIM + 4*d4]);
                m[4*d4+0] += r * w.x; m[4*d4+1] += r * w.y;
                m[4*d4+2] += r * w.z; m[4*d4+3] += r * w.w;
            }
        }
    }
    #pragma unroll
    for (int d = 0; d < DDIM; d++)
        g_msgB[(size_t)d * NROWS + row] = tf32_rna(m[d]);
}

// ==================== Kernel 2: agg (round-14 mainloop) + anti-spill fused update ====
__device__ __forceinline__ void fill_stage2(const float* __restrict__ adj, size_t rowBase,
                                            int t2, uint32_t stage, int tid)
{
    const float* aSrc = adj + rowBase * NROWS + (size_t)t2 * (2 * BK);
    #pragma unroll
    for (int i = 0; i < 8; i++) {                     // A: 2048 16B chunks
        int c = tid + 256 * i;
        int sub = c >> 10, w = c & 1023;
        int r = w >> 3, k4 = w & 7;
        uint32_t dst = stage + sub * SUBA + ((r * 8 + (k4 ^ (r & 7))) << 4);
        cp16(dst, aSrc + (size_t)r * NROWS + sub * BK + (k4 << 2));
    }
    #pragma unroll
    for (int i = 0; i < 2; i++) {                     // B: 512 chunks (2 x 32 rows)
        int c = tid + 256 * i;
        int sub = c >> 8, w = c & 255;
        int r = w >> 3, k4 = w & 7;
        uint32_t dst = stage + 2 * SUBA + sub * SUBB + ((r * 8 + (k4 ^ (r & 7))) << 4);
        cp16(dst, g_msgB + (size_t)r * NROWS + (size_t)t2 * (2 * BK) + sub * BK + (k4 << 2));
    }
    asm volatile("cp.async.commit_group;" ::: "memory");
}

__global__ __launch_bounds__(256, 1) void agg_kernel(
    const float* __restrict__ adj,   const float* __restrict__ states,
    const float* __restrict__ uW1,   const float* __restrict__ ub1,
    const float* __restrict__ uW2,   const float* __restrict__ ub2,
    float* __restrict__ out)
{
    extern __shared__ char smem[];
    uint32_t sraw = (uint32_t)__cvta_generic_to_shared(smem);
    const uint32_t stage0 = (sraw + 1023u) & ~1023u;

    const int tid  = threadIdx.x;
    const int wid  = tid >> 5;
    const int lane = tid & 31;
    const size_t rowBase = (size_t)blockIdx.x * 128;

    const int jm = lane >> 3;        // matrix index 0..3
    const int qm = lane & 7;         // row within matrix
    const int arow = wid * 16 + (jm >> 1) * 8 + qm;    // A row for this lane

    float acc[4][4];
    #pragma unroll
    for (int nt = 0; nt < 4; nt++)
        #pragma unroll
        for (int e = 0; e < 4; e++) acc[nt][e] = 0.f;
    float dlo = 0.f, dhi = 0.f;      // degree partials

    for (int t = 0; t < STAGES - 1; t++)
        fill_stage2(adj, rowBase, t, stage0 + t * STAGE_BYTES, tid);

    int bufC = 0;                    // compute slot (wraps mod 5)
    int bufF = STAGES - 1;           // fill slot
    for (int kt2 = 0; kt2 < NT2; kt2++) {
        asm volatile("cp.async.wait_group %0;" :: "n"(STAGES - 2) : "memory");
        __syncthreads();

        const int nxt = kt2 + STAGES - 1;
        if (nxt < NT2)
            fill_stage2(adj, rowBase, nxt, stage0 + (uint32_t)bufF * STAGE_BYTES, tid);
        if (++bufF == STAGES) bufF = 0;

        const uint32_t stg = stage0 + (uint32_t)bufC * STAGE_BYTES;
        if (++bufC == STAGES) bufC = 0;

        #pragma unroll
        for (int sub = 0; sub < 2; sub++) {
            const uint32_t sA = stg + sub * SUBA;
            const uint32_t sB = stg + 2 * SUBA + sub * SUBB;
            #pragma unroll
            for (int s = 0; s < 4; s++) {
                const int ch = 2 * s + (jm & 1);
                uint32_t a0, a1, a2, a3;
                ldsm_x4(a0, a1, a2, a3, sA + ((arow * 8 + (ch ^ (arow & 7))) << 4));
                dlo += __uint_as_float(a0) + __uint_as_float(a1);
                dhi += __uint_as_float(a2) + __uint_as_float(a3);
                uint32_t b[8];
                {
                    const int nr0 = (jm >> 1) * 8 + qm;            // tiles 0,1
                    ldsm_x4(b[0], b[1], b[2], b[3],
                            sB + ((nr0 * 8 + (ch ^ (nr0 & 7))) << 4));
                    const int nr1 = 16 + (jm >> 1) * 8 + qm;        // tiles 2,3
                    ldsm_x4(b[4], b[5], b[6], b[7],
                            sB + ((nr1 * 8 + (ch ^ (nr1 & 7))) << 4));
                }
                #pragma unroll
                for (int nt = 0; nt < 4; nt++)
                    mma_tf32(acc[nt], a0, a2, a1, a3, b[2*nt], b[2*nt+1]);
            }
        }
    }
    asm volatile("cp.async.wait_group 0;" ::: "memory");

    // degree reduce across the 4 lanes sharing each row
    dlo += __shfl_xor_sync(0xffffffffu, dlo, 1);
    dlo += __shfl_xor_sync(0xffffffffu, dlo, 2);
    dhi += __shfl_xor_sync(0xffffffffu, dhi, 1);
    dhi += __shfl_xor_sync(0xffffffffu, dhi, 2);
    const float rdlo = 1.0f / fmaxf(dlo, 1.0f);
    const float rdhi = 1.0f / fmaxf(dhi, 1.0f);
    __syncthreads();                                   // pipeline smem now dead

    // ---------- epilogue smem layout (reuses pipeline area) ----------
    // [sW1u 64x128 = 32KB][sW2u 128x32 = 16KB][sAgg 128x33][sSt 128x33][ex 4x64x33]
    float* sW1u = reinterpret_cast<float*>(smem + (stage0 - sraw));
    float* sW2u = sW1u + 2 * DDIM * HDIM;
    float* sAgg = sW2u + HDIM * DDIM;
    float* sSt  = sAgg + 128 * 33;
    float* ex   = sSt  + 128 * 33;

    // part 1: normalized agg -> sAgg (stride 33, scalar stores)
    {
        const int rloL = wid * 16 + (lane >> 2);
        const int rhiL = rloL + 8;
        const int coff = 2 * (lane & 3);
        #pragma unroll
        for (int nt = 0; nt < 4; nt++) {
            sAgg[rloL * 33 + 8 * nt + coff]     = acc[nt][0] * rdlo;
            sAgg[rloL * 33 + 8 * nt + coff + 1] = acc[nt][1] * rdlo;
            sAgg[rhiL * 33 + 8 * nt + coff]     = acc[nt][2] * rdhi;
            sAgg[rhiL * 33 + 8 * nt + coff + 1] = acc[nt][3] * rdhi;
        }
    }
    // stage states rows (float4 gmem loads, scalar smem stores)
    for (int i4 = tid; i4 < 128 * 8; i4 += 256) {
        const int r = i4 >> 3, c4 = i4 & 7;
        float4 v = *reinterpret_cast<const float4*>(states + (rowBase + r) * DDIM + 4 * c4);
        float* dst = &sSt[r * 33 + 4 * c4];
        dst[0] = v.x; dst[1] = v.y; dst[2] = v.z; dst[3] = v.w;
    }
    // weights
    for (int i = tid; i < 2 * DDIM * HDIM; i += 256) sW1u[i] = uW1[i];
    for (int i = tid; i < HDIM * DDIM; i += 256)     sW2u[i] = uW2[i];
    __syncthreads();

    // part 2: update MLP, warp-sliced (q uniform per warp), x streamed from smem
    const int g2 = wid >> 2, q = wid & 3;
    #pragma unroll
    for (int half = 0; half < 2; half++) {
        const int rowL = half * 64 + g2 * 32 + lane;   // 0..127

        float hid[32];
        #pragma unroll
        for (int h4 = 0; h4 < 8; h4++) {
            float4 b = __ldg(reinterpret_cast<const float4*>(ub1 + q * 32) + h4);
            hid[4*h4+0] = b.x; hid[4*h4+1] = b.y; hid[4*h4+2] = b.z; hid[4*h4+3] = b.w;
        }
        #pragma unroll
        for (int j = 0; j < DDIM; j++) {               // states part
            const float xj = sSt[rowL * 33 + j];
            #pragma unroll
            for (int h4 = 0; h4 < 8; h4++) {
                float4 w = *reinterpret_cast<const float4*>(&sW1u[j * HDIM + q * 32 + 4 * h4]);
                hid[4*h4+0] += xj * w.x; hid[4*h4+1] += xj * w.y;
                hid[4*h4+2] += xj * w.z; hid[4*h4+3] += xj * w.w;
            }
        }
        #pragma unroll
        for (int j = 0; j < DDIM; j++) {               // aggregated part
            const float xj = sAgg[rowL * 33 + j];
            #pragma unroll
            for (int h4 = 0; h4 < 8; h4++) {
                float4 w = *reinterpret_cast<const float4*>(&sW1u[(DDIM + j) * HDIM + q * 32 + 4 * h4]);
                hid[4*h4+0] += xj * w.x; hid[4*h4+1] += xj * w.y;
                hid[4*h4+2] += xj * w.z; hid[4*h4+3] += xj * w.w;
            }
        }
        float m[DDIM];
        #pragma unroll
        for (int d = 0; d < DDIM; d++) m[d] = 0.f;
        #pragma unroll
        for (int h = 0; h < 32; h++) {
            float r = fmaxf(hid[h], 0.f);
            #pragma unroll
            for (int d4 = 0; d4 < 8; d4++) {
                float4 w = *reinterpret_cast<const float4*>(&sW2u[(q * 32 + h) * DDIM + 4 * d4]);
                m[4*d4+0] += r * w.x; m[4*d4+1] += r * w.y;
                m[4*d4+2] += r * w.z; m[4*d4+3] += r * w.w;
            }
        }
        const int rowE = g2 * 32 + lane;               // 0..63 within half
        #pragma unroll
        for (int d = 0; d < DDIM; d++)
            ex[(q * 64 + rowE) * 33 + d] = m[d];
        __syncthreads();

        const int row2 = tid >> 2;                      // 0..63
        const int dg   = (tid & 3) * 8;
        const size_t rowG = rowBase + half * 64 + row2;
        float o[8];
        #pragma unroll
        for (int e = 0; e < 8; e++) {
            const int d = dg + e;
            float v = __ldg(&ub2[d]);
            #pragma unroll
            for (int qq = 0; qq < 4; qq++)
                v += ex[(qq * 64 + row2) * 33 + d];
            o[e] = v;
        }
        float4* op = reinterpret_cast<float4*>(out + rowG * DDIM + dg);
        op[0] = make_float4(o[0], o[1], o[2], o[3]);
        op[1] = make_float4(o[4], o[5], o[6], o[7]);
        __syncthreads();                                // ex reuse next half
    }
}

// ==================== launch ====================
extern "C" void kernel_launch(void* const* d_in, const int* in_sizes, int n_in,
                              void* d_out, int out_size)
{
    const float* states = (const float*)d_in[0];
    const float* adj    = (const float*)d_in[1];
    const float* mW1    = (const float*)d_in[2];
    const float* mb1    = (const float*)d_in[3];
    const float* mW2    = (const float*)d_in[4];
    const float* mb2    = (const float*)d_in[5];
    const float* uW1    = (const float*)d_in[6];
    const float* ub1    = (const float*)d_in[7];
    const float* uW2    = (const float*)d_in[8];
    const float* ub2    = (const float*)d_in[9];
    float* out = (float*)d_out;

    cudaFuncSetAttribute(agg_kernel, cudaFuncAttributeMaxDynamicSharedMemorySize, SMEM_TOTAL);

    msg_kernel<<<NROWS / 128, 128>>>(states, mW1, mb1, mW2, mb2);
    agg_kernel<<<NROWS / 128, 256, SMEM_TOTAL>>>(adj, states, uW1, ub1, uW2, ub2, out);
}

// round 16
// speedup vs baseline: 1.1428x; 1.1428x over previous
#include <cuda_runtime.h>
#include <cstdint>

#define NROWS 16384
#define DDIM  32
#define HDIM  128
#define BK    32                 // K floats per sub-tile -> 128B rows
#define BN    32                 // B rows: 32 msg cols (degree from A-side FADD)
#define STAGES 5                 // each stage = 2 sub-tiles (64 k-floats)
#define NT2   (NROWS / (2 * BK)) // 256 double-tiles
#define SUBA  (128 * 128)        // 16384 per A sub-tile
#define SUBB  (BN * 128)         // 4096 per B sub-tile
#define STAGE_BYTES (2 * SUBA + 2 * SUBB)           // 40960
#define SMEM_TOTAL  (1024 + STAGES * STAGE_BYTES)   // 205824

// tensor-upd smem layout (offsets from 1024-aligned base)
#define UPDT_SX 0                // x tile: 2 sub-tiles x 16KB (k = j 0..63)
#define UPDT_W1 32768            // W1^T:   2 sub-tiles x 16KB (rows h, k j)
#define UPDT_W2 65536            // W2^T:   4 sub-tiles x 4KB  (rows d, k h)
#define UPDT_H  81920            // hidden: 4 sub-tiles x 16KB (rows r, k h)
#define UPDT_BYTES (1024 + 81920 + 65536)   // 148480

// device scratch
__device__ float g_msgB[BN * NROWS];   // [col][k]; 32 tf32 msg columns
__device__ float g_agg [NROWS * DDIM];

// ---------------- PTX helpers ----------------
__device__ __forceinline__ void cp16(uint32_t dst, const void* src) {
    asm volatile("cp.async.cg.shared.global [%0], [%1], 16;" :: "r"(dst), "l"(src) : "memory");
}
__device__ __forceinline__ float tf32_rna(float x) {
    uint32_t r;
    asm("cvt.rna.tf32.f32 %0, %1;" : "=r"(r) : "f"(x));
    return __uint_as_float(r);
}
__device__ __forceinline__ void ldsm_x4(uint32_t& r0, uint32_t& r1, uint32_t& r2, uint32_t& r3,
                                        uint32_t addr) {
    asm volatile("ldmatrix.sync.aligned.m8n8.x4.shared.b16 {%0,%1,%2,%3}, [%4];"
                 : "=r"(r0), "=r"(r1), "=r"(r2), "=r"(r3) : "r"(addr));
}
__device__ __forceinline__ void mma_tf32(float* c, uint32_t a0, uint32_t a1,
                                         uint32_t a2, uint32_t a3,
                                         uint32_t b0, uint32_t b1) {
    asm volatile(
        "mma.sync.aligned.m16n8k8.row.col.f32.tf32.tf32.f32 "
        "{%0,%1,%2,%3}, {%4,%5,%6,%7}, {%8,%9}, {%0,%1,%2,%3};"
        : "+f"(c[0]), "+f"(c[1]), "+f"(c[2]), "+f"(c[3])
        : "r"(a0), "r"(a1), "r"(a2), "r"(a3), "r"(b0), "r"(b1));
}

// ==================== Kernel 1: message MLP (round-9 proven) ====================
__global__ __launch_bounds__(128) void msg_kernel(
    const float* __restrict__ states, const float* __restrict__ W1,
    const float* __restrict__ b1,     const float* __restrict__ W2,
    const float* __restrict__ b2)
{
    __shared__ float sW1[DDIM * HDIM];
    __shared__ float sW2[HDIM * DDIM];
    const int tid = threadIdx.x;
    for (int i = tid; i < DDIM * HDIM; i += 128) sW1[i] = W1[i];
    for (int i = tid; i < HDIM * DDIM; i += 128) sW2[i] = W2[i];
    __syncthreads();

    const int row = blockIdx.x * 128 + tid;
    float s[DDIM];
    const float4* sp = reinterpret_cast<const float4*>(states + (size_t)row * DDIM);
    #pragma unroll
    for (int j4 = 0; j4 < DDIM / 4; j4++) {
        float4 v = sp[j4];
        s[4*j4+0] = v.x; s[4*j4+1] = v.y; s[4*j4+2] = v.z; s[4*j4+3] = v.w;
    }
    float m[DDIM];
    #pragma unroll
    for (int d = 0; d < DDIM; d++) m[d] = __ldg(&b2[d]);

    #pragma unroll 4
    for (int hg = 0; hg < HDIM / 4; hg++) {
        float4 hid = __ldg(reinterpret_cast<const float4*>(b1) + hg);
        #pragma unroll
        for (int j = 0; j < DDIM; j++) {
            float4 w = *reinterpret_cast<const float4*>(&sW1[j * HDIM + 4 * hg]);
            hid.x += s[j] * w.x; hid.y += s[j] * w.y;
            hid.z += s[j] * w.z; hid.w += s[j] * w.w;
        }
        float rr[4] = {fmaxf(hid.x, 0.f), fmaxf(hid.y, 0.f),
                       fmaxf(hid.z, 0.f), fmaxf(hid.w, 0.f)};
        #pragma unroll
        for (int e = 0; e < 4; e++) {
            float r = rr[e];
            #pragma unroll
            for (int d4 = 0; d4 < DDIM / 4; d4++) {
                float4 w = *reinterpret_cast<const float4*>(&sW2[(4*hg+e) * DDIM + 4*d4]);
                m[4*d4+0] += r * w.x; m[4*d4+1] += r * w.y;
                m[4*d4+2] += r * w.z; m[4*d4+3] += r * w.w;
            }
        }
    }
    #pragma unroll
    for (int d = 0; d < DDIM; d++)
        g_msgB[(size_t)d * NROWS + row] = tf32_rna(m[d]);
}

// ==================== Kernel 2: tf32 aggregation (round-14 exact) ====================
__device__ __forceinline__ void fill_stage2(const float* __restrict__ adj, size_t rowBase,
                                            int t2, uint32_t stage, int tid)
{
    const float* aSrc = adj + rowBase * NROWS + (size_t)t2 * (2 * BK);
    #pragma unroll
    for (int i = 0; i < 8; i++) {                     // A: 2048 16B chunks
        int c = tid + 256 * i;
        int sub = c >> 10, w = c & 1023;
        int r = w >> 3, k4 = w & 7;
        uint32_t dst = stage + sub * SUBA + ((r * 8 + (k4 ^ (r & 7))) << 4);
        cp16(dst, aSrc + (size_t)r * NROWS + sub * BK + (k4 << 2));
    }
    #pragma unroll
    for (int i = 0; i < 2; i++) {                     // B: 512 chunks (2 x 32 rows)
        int c = tid + 256 * i;
        int sub = c >> 8, w = c & 255;
        int r = w >> 3, k4 = w & 7;
        uint32_t dst = stage + 2 * SUBA + sub * SUBB + ((r * 8 + (k4 ^ (r & 7))) << 4);
        cp16(dst, g_msgB + (size_t)r * NROWS + (size_t)t2 * (2 * BK) + sub * BK + (k4 << 2));
    }
    asm volatile("cp.async.commit_group;" ::: "memory");
}

__global__ __launch_bounds__(256, 1) void agg_kernel(const float* __restrict__ adj)
{
    extern __shared__ char smem[];
    uint32_t sraw = (uint32_t)__cvta_generic_to_shared(smem);
    const uint32_t stage0 = (sraw + 1023u) & ~1023u;

    const int tid  = threadIdx.x;
    const int wid  = tid >> 5;
    const int lane = tid & 31;
    const size_t rowBase = (size_t)blockIdx.x * 128;

    const int jm = lane >> 3;        // matrix index 0..3
    const int qm = lane & 7;         // row within matrix
    const int arow = wid * 16 + (jm >> 1) * 8 + qm;    // A row for this lane

    float acc[4][4];
    #pragma unroll
    for (int nt = 0; nt < 4; nt++)
        #pragma unroll
        for (int e = 0; e < 4; e++) acc[nt][e] = 0.f;
    float dlo = 0.f, dhi = 0.f;      // degree partials

    for (int t = 0; t < STAGES - 1; t++)
        fill_stage2(adj, rowBase, t, stage0 + t * STAGE_BYTES, tid);

    int bufC = 0;
    int bufF = STAGES - 1;
    for (int kt2 = 0; kt2 < NT2; kt2++) {
        asm volatile("cp.async.wait_group %0;" :: "n"(STAGES - 2) : "memory");
        __syncthreads();

        const int nxt = kt2 + STAGES - 1;
        if (nxt < NT2)
            fill_stage2(adj, rowBase, nxt, stage0 + (uint32_t)bufF * STAGE_BYTES, tid);
        if (++bufF == STAGES) bufF = 0;

        const uint32_t stg = stage0 + (uint32_t)bufC * STAGE_BYTES;
        if (++bufC == STAGES) bufC = 0;

        #pragma unroll
        for (int sub = 0; sub < 2; sub++) {
            const uint32_t sA = stg + sub * SUBA;
            const uint32_t sB = stg + 2 * SUBA + sub * SUBB;
            #pragma unroll
            for (int s = 0; s < 4; s++) {
                const int ch = 2 * s + (jm & 1);
                uint32_t a0, a1, a2, a3;
                ldsm_x4(a0, a1, a2, a3, sA + ((arow * 8 + (ch ^ (arow & 7))) << 4));
                dlo += __uint_as_float(a0) + __uint_as_float(a1);
                dhi += __uint_as_float(a2) + __uint_as_float(a3);
                uint32_t b[8];
                {
                    const int nr0 = (jm >> 1) * 8 + qm;
                    ldsm_x4(b[0], b[1], b[2], b[3],
                            sB + ((nr0 * 8 + (ch ^ (nr0 & 7))) << 4));
                    const int nr1 = 16 + (jm >> 1) * 8 + qm;
                    ldsm_x4(b[4], b[5], b[6], b[7],
                            sB + ((nr1 * 8 + (ch ^ (nr1 & 7))) << 4));
                }
                #pragma unroll
                for (int nt = 0; nt < 4; nt++)
                    mma_tf32(acc[nt], a0, a2, a1, a3, b[2*nt], b[2*nt+1]);
            }
        }
    }

    dlo += __shfl_xor_sync(0xffffffffu, dlo, 1);
    dlo += __shfl_xor_sync(0xffffffffu, dlo, 2);
    dhi += __shfl_xor_sync(0xffffffffu, dhi, 1);
    dhi += __shfl_xor_sync(0xffffffffu, dhi, 2);
    const float rdlo = 1.0f / fmaxf(dlo, 1.0f);
    const float rdhi = 1.0f / fmaxf(dhi, 1.0f);

    const size_t rlo = rowBase + (size_t)(wid * 16 + (lane >> 2));
    const size_t rhi = rlo + 8;
    const int coff = 2 * (lane & 3);
    #pragma unroll
    for (int nt = 0; nt < 4; nt++) {
        float2 olo = {acc[nt][0] * rdlo, acc[nt][1] * rdlo};
        float2 ohi = {acc[nt][2] * rdhi, acc[nt][3] * rdhi};
        *reinterpret_cast<float2*>(&g_agg[rlo * DDIM + 8 * nt + coff]) = olo;
        *reinterpret_cast<float2*>(&g_agg[rhi * DDIM + 8 * nt + coff]) = ohi;
    }
}

// ==================== Kernel 3: update MLP on tensor cores ====================
// GEMM1: hidden[128r x 128h] = x[128r x 64j] @ W1T[128h x 64j]^T   (tf32 mma)
// GEMM2: out  [128r x 32d ] = relu(hidden) @ W2T[32d x 128h]^T
__global__ __launch_bounds__(256, 1) void updt_kernel(
    const float* __restrict__ states,
    const float* __restrict__ uW1, const float* __restrict__ ub1,
    const float* __restrict__ uW2, const float* __restrict__ ub2,
    float* __restrict__ out)
{
    extern __shared__ char smem[];
    uint32_t sraw = (uint32_t)__cvta_generic_to_shared(smem);
    const uint32_t base = (sraw + 1023u) & ~1023u;
    char* sb = smem + (base - sraw);

    const int tid  = threadIdx.x;
    const int wid  = tid >> 5;
    const int lane = tid & 31;
    const size_t rowBase = (size_t)blockIdx.x * 128;

    // ---- stage x = [states | agg] as 2 k-sub-tiles, rna-rounded ----
    for (int i = tid; i < 2048; i += 256) {
        const int r = i >> 4, c4 = i & 15;          // c4: float4 chunk of j (0..15)
        float4 v;
        if (c4 < 8) v = *reinterpret_cast<const float4*>(states + (rowBase + r) * DDIM + 4 * c4);
        else        v = *reinterpret_cast<const float4*>(g_agg  + (rowBase + r) * DDIM + 4 * (c4 - 8));
        v.x = tf32_rna(v.x); v.y = tf32_rna(v.y); v.z = tf32_rna(v.z); v.w = tf32_rna(v.w);
        const int sub = c4 >> 3, k4 = c4 & 7;
        *reinterpret_cast<float4*>(sb + UPDT_SX + sub * 16384
                                   + ((r * 8 + (k4 ^ (r & 7))) << 4)) = v;
    }
    // ---- W1^T: rows h, k j (transpose of uW1[j][h]) ----
    for (int i = tid; i < 2 * DDIM * HDIM; i += 256) {
        const int j = i >> 7, h = i & 127;          // coalesced read of uW1
        const float w = tf32_rna(uW1[i]);
        const int sub = j >> 5, k4 = (j & 31) >> 2, e = j & 3;
        *reinterpret_cast<float*>(sb + UPDT_W1 + sub * 16384
                                  + ((h * 8 + (k4 ^ (h & 7))) << 4) + e * 4) = w;
    }
    // ---- W2^T: rows d, k h (transpose of uW2[h][d]) ----
    for (int i = tid; i < HDIM * DDIM; i += 256) {
        const int h = i >> 5, d = i & 31;           // coalesced read of uW2
        const float w = tf32_rna(uW2[i]);
        const int sub = h >> 5, k4 = (h & 31) >> 2, e = h & 3;
        *reinterpret_cast<float*>(sb + UPDT_W2 + sub * 4096
                                  + ((d * 8 + (k4 ^ (d & 7))) << 4) + e * 4) = w;
    }
    __syncthreads();

    const int jm = lane >> 3;
    const int qm = lane & 7;
    const int arow = wid * 16 + (jm >> 1) * 8 + qm;

    // ---- GEMM1 ----
    float acc1[16][4];
    #pragma unroll
    for (int nt = 0; nt < 16; nt++)
        #pragma unroll
        for (int e = 0; e < 4; e++) acc1[nt][e] = 0.f;

    #pragma unroll
    for (int sub = 0; sub < 2; sub++) {
        #pragma unroll
        for (int s = 0; s < 4; s++) {
            const int ch = 2 * s + (jm & 1);
            uint32_t a0, a1, a2, a3;
            ldsm_x4(a0, a1, a2, a3, base + UPDT_SX + sub * 16384
                    + ((arow * 8 + (ch ^ (arow & 7))) << 4));
            #pragma unroll
            for (int g = 0; g < 8; g++) {
                const int nr = g * 16 + (jm >> 1) * 8 + qm;
                uint32_t b0, b1, b2, b3;
                ldsm_x4(b0, b1, b2, b3, base + UPDT_W1 + sub * 16384
                        + ((nr * 8 + (ch ^ (nr & 7))) << 4));
                mma_tf32(acc1[2*g],     a0, a2, a1, a3, b0, b1);
                mma_tf32(acc1[2*g + 1], a0, a2, a1, a3, b2, b3);
            }
        }
    }

    // ---- bias + relu + store hidden (rna) ----
    const int r1 = wid * 16 + (lane >> 2);
    const int r2 = r1 + 8;
    const int cbase = 2 * (lane & 3);
    #pragma unroll
    for (int nt = 0; nt < 16; nt++) {
        const int c0 = nt * 8 + cbase;
        const float b0 = __ldg(&ub1[c0]);
        const float b1 = __ldg(&ub1[c0 + 1]);
        const float h00 = fmaxf(acc1[nt][0] + b0, 0.f);
        const float h01 = fmaxf(acc1[nt][1] + b1, 0.f);
        const float h10 = fmaxf(acc1[nt][2] + b0, 0.f);
        const float h11 = fmaxf(acc1[nt][3] + b1, 0.f);
        const int sub = c0 >> 5, k4 = (c0 & 31) >> 2, e = c0 & 3;   // e in {0,2}
        *reinterpret_cast<float2*>(sb + UPDT_H + sub * 16384
                                   + ((r1 * 8 + (k4 ^ (r1 & 7))) << 4) + e * 4)
            = make_float2(tf32_rna(h00), tf32_rna(h01));
        *reinterpret_cast<float2*>(sb + UPDT_H + sub * 16384
                                   + ((r2 * 8 + (k4 ^ (r2 & 7))) << 4) + e * 4)
            = make_float2(tf32_rna(h10), tf32_rna(h11));
    }
    __syncthreads();

    // ---- GEMM2 ----
    float acc2[4][4];
    #pragma unroll
    for (int nt = 0; nt < 4; nt++)
        #pragma unroll
        for (int e = 0; e < 4; e++) acc2[nt][e] = 0.f;

    #pragma unroll
    for (int sub = 0; sub < 4; sub++) {
        #pragma unroll
        for (int s = 0; s < 4; s++) {
            const int ch = 2 * s + (jm & 1);
            uint32_t a0, a1, a2, a3;
            ldsm_x4(a0, a1, a2, a3, base + UPDT_H + sub * 16384
                    + ((arow * 8 + (ch ^ (arow & 7))) << 4));
            #pragma unroll
            for (int g = 0; g < 2; g++) {
                const int nr = g * 16 + (jm >> 1) * 8 + qm;
                uint32_t b0, b1, b2, b3;
                ldsm_x4(b0, b1, b2, b3, base + UPDT_W2 + sub * 4096
                        + ((nr * 8 + (ch ^ (nr & 7))) << 4));
                mma_tf32(acc2[2*g],     a0, a2, a1, a3, b0, b1);
                mma_tf32(acc2[2*g + 1], a0, a2, a1, a3, b2, b3);
            }
        }
    }

    // ---- bias + store out ----
    #pragma unroll
    for (int nt = 0; nt < 4; nt++) {
        const int c0 = nt * 8 + cbase;
        const float b0 = __ldg(&ub2[c0]);
        const float b1 = __ldg(&ub2[c0 + 1]);
        *reinterpret_cast<float2*>(out + (rowBase + r1) * DDIM + c0)
            = make_float2(acc2[nt][0] + b0, acc2[nt][1] + b1);
        *reinterpret_cast<float2*>(out + (rowBase + r2) * DDIM + c0)
            = make_float2(acc2[nt][2] + b0, acc2[nt][3] + b1);
    }
}

// ==================== launch ====================
extern "C" void kernel_launch(void* const* d_in, const int* in_sizes, int n_in,
                              void* d_out, int out_size)
{
    const float* states = (const float*)d_in[0];
    const float* adj    = (const float*)d_in[1];
    const float* mW1    = (const float*)d_in[2];
    const float* mb1    = (const float*)d_in[3];
    const float* mW2    = (const float*)d_in[4];
    const float* mb2    = (const float*)d_in[5];
    const float* uW1    = (const float*)d_in[6];
    const float* ub1    = (const float*)d_in[7];
    const float* uW2    = (const float*)d_in[8];
    const float* ub2    = (const float*)d_in[9];
    float* out = (float*)d_out;

    cudaFuncSetAttribute(agg_kernel,  cudaFuncAttributeMaxDynamicSharedMemorySize, SMEM_TOTAL);
    cudaFuncSetAttribute(updt_kernel, cudaFuncAttributeMaxDynamicSharedMemorySize, UPDT_BYTES);

    msg_kernel<<<NROWS / 128, 128>>>(states, mW1, mb1, mW2, mb2);
    agg_kernel<<<NROWS / 128, 256, SMEM_TOTAL>>>(adj);
    updt_kernel<<<NROWS / 128, 256, UPDT_BYTES>>>(states, uW1, ub1, uW2, ub2, out);
}

// round 17
// speedup vs baseline: 1.1704x; 1.0242x over previous
#include <cuda_runtime.h>
#include <cstdint>

#define NROWS 16384
#define DDIM  32
#define HDIM  128
#define BK    32                 // K floats per sub-tile -> 128B rows
#define BN    32                 // B rows: 32 msg cols (degree from A-side FADD)
#define STAGES 5                 // each stage = 2 sub-tiles (64 k-floats)
#define NT2   (NROWS / (2 * BK)) // 256 double-tiles
#define SUBA  (128 * 128)        // 16384 per A sub-tile
#define SUBB  (BN * 128)         // 4096 per B sub-tile
#define STAGE_BYTES (2 * SUBA + 2 * SUBB)           // 40960
#define SMEM_TOTAL  (1024 + STAGES * STAGE_BYTES)   // 205824

// tensor-upd smem layout (offsets from 1024-aligned base)
#define UPDT_SX 0
#define UPDT_W1 32768
#define UPDT_W2 65536
#define UPDT_H  81920
#define UPDT_BYTES (1024 + 81920 + 65536)   // 148480

// tensor-msg smem layout
#define MSGT_SX 0                // x: 1 sub-tile 16KB (k=j 0..31)
#define MSGT_W1 16384            // W1^T: 1 sub-tile 16KB (rows h, k j)
#define MSGT_W2 32768            // W2^T: 4 x 4KB (rows d, k h)
#define MSGT_H  49152            // hidden: 4 x 16KB
#define MSGT_BYTES (1024 + 49152 + 65536)   // 115712

// device scratch
__device__ float g_msgB[BN * NROWS];   // [col][k]; 32 tf32 msg columns
__device__ float g_agg [NROWS * DDIM];

// ---------------- PTX helpers ----------------
__device__ __forceinline__ void cp16(uint32_t dst, const void* src) {
    asm volatile("cp.async.cg.shared.global [%0], [%1], 16;" :: "r"(dst), "l"(src) : "memory");
}
__device__ __forceinline__ float tf32_rna(float x) {
    uint32_t r;
    asm("cvt.rna.tf32.f32 %0, %1;" : "=r"(r) : "f"(x));
    return __uint_as_float(r);
}
__device__ __forceinline__ void ldsm_x4(uint32_t& r0, uint32_t& r1, uint32_t& r2, uint32_t& r3,
                                        uint32_t addr) {
    asm volatile("ldmatrix.sync.aligned.m8n8.x4.shared.b16 {%0,%1,%2,%3}, [%4];"
                 : "=r"(r0), "=r"(r1), "=r"(r2), "=r"(r3) : "r"(addr));
}
__device__ __forceinline__ void mma_tf32(float* c, uint32_t a0, uint32_t a1,
                                         uint32_t a2, uint32_t a3,
                                         uint32_t b0, uint32_t b1) {
    asm volatile(
        "mma.sync.aligned.m16n8k8.row.col.f32.tf32.tf32.f32 "
        "{%0,%1,%2,%3}, {%4,%5,%6,%7}, {%8,%9}, {%0,%1,%2,%3};"
        : "+f"(c[0]), "+f"(c[1]), "+f"(c[2]), "+f"(c[3])
        : "r"(a0), "r"(a1), "r"(a2), "r"(a3), "r"(b0), "r"(b1));
}

// ==================== Kernel 1: message MLP on tensor cores ====================
// GEMM1: hidden[128r x 128h] = x[128r x 32j] @ W1T[128h x 32j]^T
// GEMM2: msg  [128r x 32d ] = relu(hidden) @ W2T[32d x 128h]^T -> g_msgB transposed
__global__ __launch_bounds__(256, 1) void msgt_kernel(
    const float* __restrict__ states,
    const float* __restrict__ mW1, const float* __restrict__ mb1,
    const float* __restrict__ mW2, const float* __restrict__ mb2)
{
    extern __shared__ char smem[];
    uint32_t sraw = (uint32_t)__cvta_generic_to_shared(smem);
    const uint32_t base = (sraw + 1023u) & ~1023u;
    char* sb = smem + (base - sraw);

    const int tid  = threadIdx.x;
    const int wid  = tid >> 5;
    const int lane = tid & 31;
    const size_t rowBase = (size_t)blockIdx.x * 128;

    // stage x = states rows (rna-rounded), k = j 0..31
    for (int i = tid; i < 1024; i += 256) {
        const int r = i >> 3, k4 = i & 7;
        float4 v = *reinterpret_cast<const float4*>(states + (rowBase + r) * DDIM + 4 * k4);
        v.x = tf32_rna(v.x); v.y = tf32_rna(v.y); v.z = tf32_rna(v.z); v.w = tf32_rna(v.w);
        *reinterpret_cast<float4*>(sb + MSGT_SX + ((r * 8 + (k4 ^ (r & 7))) << 4)) = v;
    }
    // W1^T: rows h, k j (transpose of mW1[j][h])
    for (int i = tid; i < DDIM * HDIM; i += 256) {
        const int j = i >> 7, h = i & 127;
        const float w = tf32_rna(mW1[i]);
        const int k4 = j >> 2, e = j & 3;
        *reinterpret_cast<float*>(sb + MSGT_W1 + ((h * 8 + (k4 ^ (h & 7))) << 4) + e * 4) = w;
    }
    // W2^T: rows d, k h (transpose of mW2[h][d])
    for (int i = tid; i < HDIM * DDIM; i += 256) {
        const int h = i >> 5, d = i & 31;
        const float w = tf32_rna(mW2[i]);
        const int sub = h >> 5, k4 = (h & 31) >> 2, e = h & 3;
        *reinterpret_cast<float*>(sb + MSGT_W2 + sub * 4096
                                  + ((d * 8 + (k4 ^ (d & 7))) << 4) + e * 4) = w;
    }
    __syncthreads();

    const int jm = lane >> 3;
    const int qm = lane & 7;
    const int arow = wid * 16 + (jm >> 1) * 8 + qm;

    // GEMM1 (K=32: 4 mma k-steps)
    float acc1[16][4];
    #pragma unroll
    for (int nt = 0; nt < 16; nt++)
        #pragma unroll
        for (int e = 0; e < 4; e++) acc1[nt][e] = 0.f;

    #pragma unroll
    for (int s = 0; s < 4; s++) {
        const int ch = 2 * s + (jm & 1);
        uint32_t a0, a1, a2, a3;
        ldsm_x4(a0, a1, a2, a3, base + MSGT_SX + ((arow * 8 + (ch ^ (arow & 7))) << 4));
        #pragma unroll
        for (int g = 0; g < 8; g++) {
            const int nr = g * 16 + (jm >> 1) * 8 + qm;
            uint32_t b0, b1, b2, b3;
            ldsm_x4(b0, b1, b2, b3, base + MSGT_W1 + ((nr * 8 + (ch ^ (nr & 7))) << 4));
            mma_tf32(acc1[2*g],     a0, a2, a1, a3, b0, b1);
            mma_tf32(acc1[2*g + 1], a0, a2, a1, a3, b2, b3);
        }
    }

    // bias + relu + store hidden (rna)
    const int r1 = wid * 16 + (lane >> 2);
    const int r2 = r1 + 8;
    const int cbase = 2 * (lane & 3);
    #pragma unroll
    for (int nt = 0; nt < 16; nt++) {
        const int c0 = nt * 8 + cbase;
        const float b0 = __ldg(&mb1[c0]);
        const float b1 = __ldg(&mb1[c0 + 1]);
        const float h00 = fmaxf(acc1[nt][0] + b0, 0.f);
        const float h01 = fmaxf(acc1[nt][1] + b1, 0.f);
        const float h10 = fmaxf(acc1[nt][2] + b0, 0.f);
        const float h11 = fmaxf(acc1[nt][3] + b1, 0.f);
        const int sub = c0 >> 5, k4 = (c0 & 31) >> 2, e = c0 & 3;
        *reinterpret_cast<float2*>(sb + MSGT_H + sub * 16384
                                   + ((r1 * 8 + (k4 ^ (r1 & 7))) << 4) + e * 4)
            = make_float2(tf32_rna(h00), tf32_rna(h01));
        *reinterpret_cast<float2*>(sb + MSGT_H + sub * 16384
                                   + ((r2 * 8 + (k4 ^ (r2 & 7))) << 4) + e * 4)
            = make_float2(tf32_rna(h10), tf32_rna(h11));
    }
    __syncthreads();

    // GEMM2
    float acc2[4][4];
    #pragma unroll
    for (int nt = 0; nt < 4; nt++)
        #pragma unroll
        for (int e = 0; e < 4; e++) acc2[nt][e] = 0.f;

    #pragma unroll
    for (int sub = 0; sub < 4; sub++) {
        #pragma unroll
        for (int s = 0; s < 4; s++) {
            const int ch = 2 * s + (jm & 1);
            uint32_t a0, a1, a2, a3;
            ldsm_x4(a0, a1, a2, a3, base + MSGT_H + sub * 16384
                    + ((arow * 8 + (ch ^ (arow & 7))) << 4));
            #pragma unroll
            for (int g = 0; g < 2; g++) {
                const int nr = g * 16 + (jm >> 1) * 8 + qm;
                uint32_t b0, b1, b2, b3;
                ldsm_x4(b0, b1, b2, b3, base + MSGT_W2 + sub * 4096
                        + ((nr * 8 + (ch ^ (nr & 7))) << 4));
                mma_tf32(acc2[2*g],     a0, a2, a1, a3, b0, b1);
                mma_tf32(acc2[2*g + 1], a0, a2, a1, a3, b2, b3);
            }
        }
    }

    // bias + rna + TRANSPOSED store to g_msgB[col][row]
    #pragma unroll
    for (int nt = 0; nt < 4; nt++) {
        const int c0 = nt * 8 + cbase;
        const float b0 = __ldg(&mb2[c0]);
        const float b1 = __ldg(&mb2[c0 + 1]);
        g_msgB[(size_t)c0       * NROWS + rowBase + r1] = tf32_rna(acc2[nt][0] + b0);
        g_msgB[(size_t)(c0 + 1) * NROWS + rowBase + r1] = tf32_rna(acc2[nt][1] + b1);
        g_msgB[(size_t)c0       * NROWS + rowBase + r2] = tf32_rna(acc2[nt][2] + b0);
        g_msgB[(size_t)(c0 + 1) * NROWS + rowBase + r2] = tf32_rna(acc2[nt][3] + b1);
    }
}

// ==================== Kernel 2: tf32 aggregation (round-14 exact) ====================
__device__ __forceinline__ void fill_stage2(const float* __restrict__ adj, size_t rowBase,
                                            int t2, uint32_t stage, int tid)
{
    const float* aSrc = adj + rowBase * NROWS + (size_t)t2 * (2 * BK);
    #pragma unroll
    for (int i = 0; i < 8; i++) {                     // A: 2048 16B chunks
        int c = tid + 256 * i;
        int sub = c >> 10, w = c & 1023;
        int r = w >> 3, k4 = w & 7;
        uint32_t dst = stage + sub * SUBA + ((r * 8 + (k4 ^ (r & 7))) << 4);
        cp16(dst, aSrc + (size_t)r * NROWS + sub * BK + (k4 << 2));
    }
    #pragma unroll
    for (int i = 0; i < 2; i++) {                     // B: 512 chunks (2 x 32 rows)
        int c = tid + 256 * i;
        int sub = c >> 8, w = c & 255;
        int r = w >> 3, k4 = w & 7;
        uint32_t dst = stage + 2 * SUBA + sub * SUBB + ((r * 8 + (k4 ^ (r & 7))) << 4);
        cp16(dst, g_msgB + (size_t)r * NROWS + (size_t)t2 * (2 * BK) + sub * BK + (k4 << 2));
    }
    asm volatile("cp.async.commit_group;" ::: "memory");
}

__global__ __launch_bounds__(256, 1) void agg_kernel(const float* __restrict__ adj)
{
    extern __shared__ char smem[];
    uint32_t sraw = (uint32_t)__cvta_generic_to_shared(smem);
    const uint32_t stage0 = (sraw + 1023u) & ~1023u;

    const int tid  = threadIdx.x;
    const int wid  = tid >> 5;
    const int lane = tid & 31;
    const size_t rowBase = (size_t)blockIdx.x * 128;

    const int jm = lane >> 3;
    const int qm = lane & 7;
    const int arow = wid * 16 + (jm >> 1) * 8 + qm;

    float acc[4][4];
    #pragma unroll
    for (int nt = 0; nt < 4; nt++)
        #pragma unroll
        for (int e = 0; e < 4; e++) acc[nt][e] = 0.f;
    float dlo = 0.f, dhi = 0.f;

    for (int t = 0; t < STAGES - 1; t++)
        fill_stage2(adj, rowBase, t, stage0 + t * STAGE_BYTES, tid);

    int bufC = 0;
    int bufF = STAGES - 1;
    for (int kt2 = 0; kt2 < NT2; kt2++) {
        asm volatile("cp.async.wait_group %0;" :: "n"(STAGES - 2) : "memory");
        __syncthreads();

        const int nxt = kt2 + STAGES - 1;
        if (nxt < NT2)
            fill_stage2(adj, rowBase, nxt, stage0 + (uint32_t)bufF * STAGE_BYTES, tid);
        if (++bufF == STAGES) bufF = 0;

        const uint32_t stg = stage0 + (uint32_t)bufC * STAGE_BYTES;
        if (++bufC == STAGES) bufC = 0;

        #pragma unroll
        for (int sub = 0; sub < 2; sub++) {
            const uint32_t sA = stg + sub * SUBA;
            const uint32_t sB = stg + 2 * SUBA + sub * SUBB;
            #pragma unroll
            for (int s = 0; s < 4; s++) {
                const int ch = 2 * s + (jm & 1);
                uint32_t a0, a1, a2, a3;
                ldsm_x4(a0, a1, a2, a3, sA + ((arow * 8 + (ch ^ (arow & 7))) << 4));
                dlo += __uint_as_float(a0) + __uint_as_float(a1);
                dhi += __uint_as_float(a2) + __uint_as_float(a3);
                uint32_t b[8];
                {
                    const int nr0 = (jm >> 1) * 8 + qm;
                    ldsm_x4(b[0], b[1], b[2], b[3],
                            sB + ((nr0 * 8 + (ch ^ (nr0 & 7))) << 4));
                    const int nr1 = 16 + (jm >> 1) * 8 + qm;
                    ldsm_x4(b[4], b[5], b[6], b[7],
                            sB + ((nr1 * 8 + (ch ^ (nr1 & 7))) << 4));
                }
                #pragma unroll
                for (int nt = 0; nt < 4; nt++)
                    mma_tf32(acc[nt], a0, a2, a1, a3, b[2*nt], b[2*nt+1]);
            }
        }
    }

    dlo += __shfl_xor_sync(0xffffffffu, dlo, 1);
    dlo += __shfl_xor_sync(0xffffffffu, dlo, 2);
    dhi += __shfl_xor_sync(0xffffffffu, dhi, 1);
    dhi += __shfl_xor_sync(0xffffffffu, dhi, 2);
    const float rdlo = 1.0f / fmaxf(dlo, 1.0f);
    const float rdhi = 1.0f / fmaxf(dhi, 1.0f);

    const size_t rlo = rowBase + (size_t)(wid * 16 + (lane >> 2));
    const size_t rhi = rlo + 8;
    const int coff = 2 * (lane & 3);
    #pragma unroll
    for (int nt = 0; nt < 4; nt++) {
        float2 olo = {acc[nt][0] * rdlo, acc[nt][1] * rdlo};
        float2 ohi = {acc[nt][2] * rdhi, acc[nt][3] * rdhi};
        *reinterpret_cast<float2*>(&g_agg[rlo * DDIM + 8 * nt + coff]) = olo;
        *reinterpret_cast<float2*>(&g_agg[rhi * DDIM + 8 * nt + coff]) = ohi;
    }
}

// ==================== Kernel 3: update MLP on tensor cores (round-16 exact) ==========
__global__ __launch_bounds__(256, 1) void updt_kernel(
    const float* __restrict__ states,
    const float* __restrict__ uW1, const float* __restrict__ ub1,
    const float* __restrict__ uW2, const float* __restrict__ ub2,
    float* __restrict__ out)
{
    extern __shared__ char smem[];
    uint32_t sraw = (uint32_t)__cvta_generic_to_shared(smem);
    const uint32_t base = (sraw + 1023u) & ~1023u;
    char* sb = smem + (base - sraw);

    const int tid  = threadIdx.x;
    const int wid  = tid >> 5;
    const int lane = tid & 31;
    const size_t rowBase = (size_t)blockIdx.x * 128;

    for (int i = tid; i < 2048; i += 256) {
        const int r = i >> 4, c4 = i & 15;
        float4 v;
        if (c4 < 8) v = *reinterpret_cast<const float4*>(states + (rowBase + r) * DDIM + 4 * c4);
        else        v = *reinterpret_cast<const float4*>(g_agg  + (rowBase + r) * DDIM + 4 * (c4 - 8));
        v.x = tf32_rna(v.x); v.y = tf32_rna(v.y); v.z = tf32_rna(v.z); v.w = tf32_rna(v.w);
        const int sub = c4 >> 3, k4 = c4 & 7;
        *reinterpret_cast<float4*>(sb + UPDT_SX + sub * 16384
                                   + ((r * 8 + (k4 ^ (r & 7))) << 4)) = v;
    }
    for (int i = tid; i < 2 * DDIM * HDIM; i += 256) {
        const int j = i >> 7, h = i & 127;
        const float w = tf32_rna(uW1[i]);
        const int sub = j >> 5, k4 = (j & 31) >> 2, e = j & 3;
        *reinterpret_cast<float*>(sb + UPDT_W1 + sub * 16384
                                  + ((h * 8 + (k4 ^ (h & 7))) << 4) + e * 4) = w;
    }
    for (int i = tid; i < HDIM * DDIM; i += 256) {
        const int h = i >> 5, d = i & 31;
        const float w = tf32_rna(uW2[i]);
        const int sub = h >> 5, k4 = (h & 31) >> 2, e = h & 3;
        *reinterpret_cast<float*>(sb + UPDT_W2 + sub * 4096
                                  + ((d * 8 + (k4 ^ (d & 7))) << 4) + e * 4) = w;
    }
    __syncthreads();

    const int jm = lane >> 3;
    const int qm = lane & 7;
    const int arow = wid * 16 + (jm >> 1) * 8 + qm;

    float acc1[16][4];
    #pragma unroll
    for (int nt = 0; nt < 16; nt++)
        #pragma unroll
        for (int e = 0; e < 4; e++) acc1[nt][e] = 0.f;

    #pragma unroll
    for (int sub = 0; sub < 2; sub++) {
        #pragma unroll
        for (int s = 0; s < 4; s++) {
            const int ch = 2 * s + (jm & 1);
            uint32_t a0, a1, a2, a3;
            ldsm_x4(a0, a1, a2, a3, base + UPDT_SX + sub * 16384
                    + ((arow * 8 + (ch ^ (arow & 7))) << 4));
            #pragma unroll
            for (int g = 0; g < 8; g++) {
                const int nr = g * 16 + (jm >> 1) * 8 + qm;
                uint32_t b0, b1, b2, b3;
                ldsm_x4(b0, b1, b2, b3, base + UPDT_W1 + sub * 16384
                        + ((nr * 8 + (ch ^ (nr & 7))) << 4));
                mma_tf32(acc1[2*g],     a0, a2, a1, a3, b0, b1);
                mma_tf32(acc1[2*g + 1], a0, a2, a1, a3, b2, b3);
            }
        }
    }

    const int r1 = wid * 16 + (lane >> 2);
    const int r2 = r1 + 8;
    const int cbase = 2 * (lane & 3);
    #pragma unroll
    for (int nt = 0; nt < 16; nt++) {
        const int c0 = nt * 8 + cbase;
        const float b0 = __ldg(&ub1[c0]);
        const float b1 = __ldg(&ub1[c0 + 1]);
        const float h00 = fmaxf(acc1[nt][0] + b0, 0.f);
        const float h01 = fmaxf(acc1[nt][1] + b1, 0.f);
        const float h10 = fmaxf(acc1[nt][2] + b0, 0.f);
        const float h11 = fmaxf(acc1[nt][3] + b1, 0.f);
        const int sub = c0 >> 5, k4 = (c0 & 31) >> 2, e = c0 & 3;
        *reinterpret_cast<float2*>(sb + UPDT_H + sub * 16384
                                   + ((r1 * 8 + (k4 ^ (r1 & 7))) << 4) + e * 4)
            = make_float2(tf32_rna(h00), tf32_rna(h01));
        *reinterpret_cast<float2*>(sb + UPDT_H + sub * 16384
                                   + ((r2 * 8 + (k4 ^ (r2 & 7))) << 4) + e * 4)
            = make_float2(tf32_rna(h10), tf32_rna(h11));
    }
    __syncthreads();

    float acc2[4][4];
    #pragma unroll
    for (int nt = 0; nt < 4; nt++)
        #pragma unroll
        for (int e = 0; e < 4; e++) acc2[nt][e] = 0.f;

    #pragma unroll
    for (int sub = 0; sub < 4; sub++) {
        #pragma unroll
        for (int s = 0; s < 4; s++) {
            const int ch = 2 * s + (jm & 1);
            uint32_t a0, a1, a2, a3;
            ldsm_x4(a0, a1, a2, a3, base + UPDT_H + sub * 16384
                    + ((arow * 8 + (ch ^ (arow & 7))) << 4));
            #pragma unroll
            for (int g = 0; g < 2; g++) {
                const int nr = g * 16 + (jm >> 1) * 8 + qm;
                uint32_t b0, b1, b2, b3;
                ldsm_x4(b0, b1, b2, b3, base + UPDT_W2 + sub * 4096
                        + ((nr * 8 + (ch ^ (nr & 7))) << 4));
                mma_tf32(acc2[2*g],     a0, a2, a1, a3, b0, b1);
                mma_tf32(acc2[2*g + 1], a0, a2, a1, a3, b2, b3);
            }
        }
    }

    #pragma unroll
    for (int nt = 0; nt < 4; nt++) {
        const int c0 = nt * 8 + cbase;
        const float b0 = __ldg(&ub2[c0]);
        const float b1 = __ldg(&ub2[c0 + 1]);
        *reinterpret_cast<float2*>(out + (rowBase + r1) * DDIM + c0)
            = make_float2(acc2[nt][0] + b0, acc2[nt][1] + b1);
        *reinterpret_cast<float2*>(out + (rowBase + r2) * DDIM + c0)
            = make_float2(acc2[nt][2] + b0, acc2[nt][3] + b1);
    }
}

// ==================== launch ====================
extern "C" void kernel_launch(void* const* d_in, const int* in_sizes, int n_in,
                              void* d_out, int out_size)
{
    const float* states = (const float*)d_in[0];
    const float* adj    = (const float*)d_in[1];
    const float* mW1    = (const float*)d_in[2];
    const float* mb1    = (const float*)d_in[3];
    const float* mW2    = (const float*)d_in[4];
    const float* mb2    = (const float*)d_in[5];
    const float* uW1    = (const float*)d_in[6];
    const float* ub1    = (const float*)d_in[7];
    const float* uW2    = (const float*)d_in[8];
    const float* ub2    = (const float*)d_in[9];
    float* out = (float*)d_out;

    cudaFuncSetAttribute(agg_kernel,  cudaFuncAttributeMaxDynamicSharedMemorySize, SMEM_TOTAL);
    cudaFuncSetAttribute(updt_kernel, cudaFuncAttributeMaxDynamicSharedMemorySize, UPDT_BYTES);
    cudaFuncSetAttribute(msgt_kernel, cudaFuncAttributeMaxDynamicSharedMemorySize, MSGT_BYTES);

    msgt_kernel<<<NROWS / 128, 256, MSGT_BYTES>>>(states, mW1, mb1, mW2, mb2);
    agg_kernel<<<NROWS / 128, 256, SMEM_TOTAL>>>(adj);
    updt_kernel<<<NROWS / 128, 256, UPDT_BYTES>>>(states, uW1, ub1, uW2, ub2, out);
}